// round 1
// baseline (speedup 1.0000x reference)
#include <cuda_runtime.h>
#include <cstdint>

typedef unsigned long long ull;

#define F_DIM 16
#define N_DIM 8192
#define D_DIM 64
#define K_DIM 512
#define DP    (D_DIM / 2)          // 32 d-pairs
#define KT    8                    // k per chunk (8 f32x2 accumulators per row)
#define THREADS 256
#define ROWS_PER_ITER (2 * THREADS)   // 512 rows per block-iteration (2 rows/thread)
#define ITERS 2                        // 1024 rows per block
#define BLOCKS_PER_F 8
#define NUM_BLOCKS (F_DIM * BLOCKS_PER_F)   // 128
#define OUT_ELEMS ((size_t)F_DIM * N_DIM * D_DIM)   // 8388608

#define SMEM_W_BYTES (DP * K_DIM * sizeof(float2))  // 131072
#define SMEM_BYTES (SMEM_W_BYTES + K_DIM * sizeof(float) + THREADS * sizeof(float))

__device__ float g_partials[NUM_BLOCKS];

// Packed fp32x2 FMA (Blackwell-only; doubles fp32 FMA throughput vs scalar FFMA).
__device__ __forceinline__ ull ffma2(ull a, ull b, ull c) {
    ull d;
    asm("fma.rn.f32x2 %0, %1, %2, %3;" : "=l"(d) : "l"(a), "l"(b), "l"(c));
    return d;
}

__device__ __forceinline__ float2 u2f(ull v) {
    float2 r;
    asm("mov.b64 {%0, %1}, %2;" : "=f"(r.x), "=f"(r.y) : "l"(v));
    return r;
}

__global__ __launch_bounds__(THREADS, 1)
void vq_kernel(const float* __restrict__ x_all,
               const float* __restrict__ w_all,
               float* __restrict__ out) {
    extern __shared__ char smem[];
    float2* w2   = (float2*)smem;                       // [DP][K_DIM]: (w[2dp][k], w[2dp+1][k])
    float* wnorm = (float*)(smem + SMEM_W_BYTES);       // [K_DIM]
    float* red   = wnorm + K_DIM;                       // [THREADS]

    const int tid = threadIdx.x;
    const int f = blockIdx.x / BLOCKS_PER_F;
    const int rowbase = (blockIdx.x % BLOCKS_PER_F) * (N_DIM / BLOCKS_PER_F);

    const float* xg = x_all + (size_t)f * N_DIM * D_DIM;
    const float* wg = w_all + (size_t)f * D_DIM * K_DIM;
    float* outf = out + (size_t)f * N_DIM * D_DIM;

    // ---- stage w[f] into smem, repacked as d-pairs -------------------------
    for (int i = tid; i < DP * K_DIM; i += THREADS) {
        int dp = i >> 9;             // / K_DIM
        int k  = i & (K_DIM - 1);
        float a = wg[(2 * dp) * K_DIM + k];
        float b = wg[(2 * dp + 1) * K_DIM + k];
        w2[i] = make_float2(a, b);
    }
    __syncthreads();

    // ---- ||w_k||^2 ---------------------------------------------------------
    for (int k = tid; k < K_DIM; k += THREADS) {
        float s = 0.f;
        #pragma unroll
        for (int dp = 0; dp < DP; ++dp) {
            float2 v = w2[dp * K_DIM + k];
            s = fmaf(v.x, v.x, s);
            s = fmaf(v.y, v.y, s);
        }
        wnorm[k] = s;
    }
    __syncthreads();

    float loss_acc = 0.f;

    for (int it = 0; it < ITERS; ++it) {
        const int r0 = rowbase + it * ROWS_PER_ITER + tid;
        const int r1 = r0 + THREADS;

        // x rows live in registers as natural (d, d+1) pairs
        ull xa[DP], xb[DP];
        {
            const ulonglong2* pa = (const ulonglong2*)(xg + (size_t)r0 * D_DIM);
            const ulonglong2* pb = (const ulonglong2*)(xg + (size_t)r1 * D_DIM);
            #pragma unroll
            for (int j = 0; j < DP / 2; ++j) {
                ulonglong2 va = pa[j]; xa[2 * j] = va.x; xa[2 * j + 1] = va.y;
                ulonglong2 vb = pb[j]; xb[2 * j] = vb.x; xb[2 * j + 1] = vb.y;
            }
        }

        float bestA = 3.4e38f, bestB = 3.4e38f;
        int idxA = 0, idxB = 0;

        for (int k0 = 0; k0 < K_DIM; k0 += KT) {
            ull accA[KT], accB[KT];
            #pragma unroll
            for (int j = 0; j < KT; ++j) { accA[j] = 0ull; accB[j] = 0ull; }

            #pragma unroll
            for (int dp = 0; dp < DP; ++dp) {
                const ulonglong2* wp = (const ulonglong2*)(w2 + dp * K_DIM + k0);
                ull xva = xa[dp], xvb = xb[dp];
                #pragma unroll
                for (int j = 0; j < KT / 2; ++j) {
                    ulonglong2 wv = wp[j];  // broadcast LDS.128: 2 k's worth of d-pairs
                    accA[2 * j]     = ffma2(xva, wv.x, accA[2 * j]);
                    accA[2 * j + 1] = ffma2(xva, wv.y, accA[2 * j + 1]);
                    accB[2 * j]     = ffma2(xvb, wv.x, accB[2 * j]);
                    accB[2 * j + 1] = ffma2(xvb, wv.y, accB[2 * j + 1]);
                }
            }

            // score = ||w||^2 - 2*dot ; argmin (first-min tie-break via strict <)
            #pragma unroll
            for (int j = 0; j < KT; ++j) {
                float wn = wnorm[k0 + j];
                float2 a = u2f(accA[j]);
                float sA = fmaf(-2.f, a.x + a.y, wn);
                if (sA < bestA) { bestA = sA; idxA = k0 + j; }
                float2 b = u2f(accB[j]);
                float sB = fmaf(-2.f, b.x + b.y, wn);
                if (sB < bestB) { bestB = sB; idxB = k0 + j; }
            }
        }

        // ---- gather codes, write output, accumulate loss -------------------
        {
            float4* oA = (float4*)(outf + (size_t)r0 * D_DIM);
            float4* oB = (float4*)(outf + (size_t)r1 * D_DIM);
            #pragma unroll
            for (int j = 0; j < DP / 2; ++j) {
                float2 qa0 = w2[(2 * j) * K_DIM + idxA];
                float2 qa1 = w2[(2 * j + 1) * K_DIM + idxA];
                float2 va0 = u2f(xa[2 * j]), va1 = u2f(xa[2 * j + 1]);
                float d;
                d = qa0.x - va0.x; loss_acc = fmaf(d, d, loss_acc);
                d = qa0.y - va0.y; loss_acc = fmaf(d, d, loss_acc);
                d = qa1.x - va1.x; loss_acc = fmaf(d, d, loss_acc);
                d = qa1.y - va1.y; loss_acc = fmaf(d, d, loss_acc);
                oA[j] = make_float4(qa0.x, qa0.y, qa1.x, qa1.y);

                float2 qb0 = w2[(2 * j) * K_DIM + idxB];
                float2 qb1 = w2[(2 * j + 1) * K_DIM + idxB];
                float2 vb0 = u2f(xb[2 * j]), vb1 = u2f(xb[2 * j + 1]);
                d = qb0.x - vb0.x; loss_acc = fmaf(d, d, loss_acc);
                d = qb0.y - vb0.y; loss_acc = fmaf(d, d, loss_acc);
                d = qb1.x - vb1.x; loss_acc = fmaf(d, d, loss_acc);
                d = qb1.y - vb1.y; loss_acc = fmaf(d, d, loss_acc);
                oB[j] = make_float4(qb0.x, qb0.y, qb1.x, qb1.y);
            }
        }
    }

    // deterministic block reduction of loss partial
    red[tid] = loss_acc;
    __syncthreads();
    #pragma unroll
    for (int s = THREADS / 2; s > 0; s >>= 1) {
        if (tid < s) red[tid] += red[tid + s];
        __syncthreads();
    }
    if (tid == 0) g_partials[blockIdx.x] = red[0];
}

__global__ void vq_finalize(float* out, int write_loss) {
    __shared__ float red[NUM_BLOCKS];
    int t = threadIdx.x;
    red[t] = g_partials[t];
    __syncthreads();
    #pragma unroll
    for (int s = NUM_BLOCKS / 2; s > 0; s >>= 1) {
        if (t < s) red[t] += red[t + s];
        __syncthreads();
    }
    if (t == 0 && write_loss) {
        // loss = q_latent + 0.25 * e_latent = 1.25 * mean((q - x)^2)
        out[OUT_ELEMS] = 1.25f * red[0] / (float)OUT_ELEMS;
    }
}

extern "C" void kernel_launch(void* const* d_in, const int* in_sizes, int n_in,
                              void* d_out, int out_size) {
    const float* x = (const float*)d_in[0];
    const float* w = (const float*)d_in[1];
    float* out = (float*)d_out;

    cudaFuncSetAttribute(vq_kernel, cudaFuncAttributeMaxDynamicSharedMemorySize,
                         (int)SMEM_BYTES);
    vq_kernel<<<NUM_BLOCKS, THREADS, SMEM_BYTES>>>(x, w, out);

    int write_loss = (out_size > (int)OUT_ELEMS) ? 1 : 0;
    vq_finalize<<<1, NUM_BLOCKS>>>(out, write_loss);
}